// round 11
// baseline (speedup 1.0000x reference)
#include <cuda_runtime.h>
#include <math.h>

// ---------------------------------------------------------------------------
// QRNN: h_t = tanh(x_t @ Wh + b + h_{t-1} @ Uh),  T=512, B=32, D=1024
// Phase B: fp32 SGEMM (R3-proven).
// Phase C: recurrence, 128 CTAs = 32 ntiles x 4 batch groups, full-K per CTA.
//          R11: per-warp dataflow -- each warp polls only its 4 producer
//          flags, stages its private k-slice (one shot, MLP=8), computes;
//          CTA barriers only around the split-K reduce.
// ---------------------------------------------------------------------------

#define TT 512
#define BB 32
#define DD 1024
#define QQ 256

#define HS_STRIDE 1036
#define PART_STRIDE 264

__device__ float g_Wh[DD * DD];
__device__ float g_Uh[DD * DD];
__device__ int   g_done[TT][4][32];   // per (t, batch-group, ntile) flag

// ------------------------- sync primitives ----------------------------------
__device__ __forceinline__ int ld_acq(const int* p) {
    int v;
    asm volatile("ld.acquire.gpu.global.s32 %0, [%1];" : "=r"(v) : "l"(p) : "memory");
    return v;
}
__device__ __forceinline__ void st_rel(int* p, int v) {
    asm volatile("st.release.gpu.global.s32 [%0], %1;" :: "l"(p), "r"(v) : "memory");
}

// --------------------------- quaternion matrix build ------------------------
// which==0 also zeroes the flag array (rides along off the critical path).
__global__ void build_qmat_kernel(const float* __restrict__ wr,
                                  const float* __restrict__ wi,
                                  const float* __restrict__ wj,
                                  const float* __restrict__ wk,
                                  int which) {
    int e = blockIdx.x * blockDim.x + threadIdx.x;
    int d = blockIdx.y;
    if (which == 0 && d == 0) {
        for (int i = e; i < TT * 4 * 32; i += 1024)
            (&g_done[0][0][0])[i] = 0;
    }
    int br = d >> 8, bc = e >> 8;
    int r = d & 255, c = e & 255;
    int comp = br ^ bc;
    int mask = (0x5390 >> (br * 4)) & 0xF;
    float s = ((mask >> bc) & 1) ? -1.0f : 1.0f;
    const float* w = (comp == 0) ? wr : (comp == 1) ? wi : (comp == 2) ? wj : wk;
    float* W = which ? g_Uh : g_Wh;
    W[d * DD + e] = s * w[r * QQ + c];
}

// --------------------------- fp32 SGEMM (R3 version) ------------------------
#define GBM 128
#define GBN 128
#define GBK 8

__global__ void __launch_bounds__(256)
sgemm_bias_kernel(const float* __restrict__ A, const float* __restrict__ bias,
                  float* __restrict__ C, int M, int N, int K) {
    __shared__ float As[2][GBK][GBM];
    __shared__ float Bs[2][GBK][GBN];
    const float* Bmat = g_Wh;

    int tid  = threadIdx.x;
    int brow = blockIdx.y, bcol = blockIdx.x;
    int arow = tid >> 1,  acol = (tid & 1) << 2;
    int brl  = tid >> 5,  bcl  = (tid & 31) << 2;

    const float* Ab = A + (size_t)(brow * GBM) * K;
    const float* Bb = Bmat + bcol * GBN;

    float4 av = *(const float4*)&Ab[(size_t)arow * K + acol];
    float4 bv = *(const float4*)&Bb[(size_t)brl * N + bcl];
    As[0][acol + 0][arow] = av.x;
    As[0][acol + 1][arow] = av.y;
    As[0][acol + 2][arow] = av.z;
    As[0][acol + 3][arow] = av.w;
    *(float4*)&Bs[0][brl][bcl] = bv;
    __syncthreads();

    int tm = (tid >> 4) << 3;
    int tn = (tid & 15) << 3;
    float acc[8][8];
#pragma unroll
    for (int i = 0; i < 8; i++)
#pragma unroll
        for (int j = 0; j < 8; j++) acc[i][j] = 0.0f;

    int nk = K / GBK;
    for (int kt = 0; kt < nk; ++kt) {
        int cur = kt & 1;
        float4 an, bn;
        if (kt + 1 < nk) {
            an = *(const float4*)&Ab[(size_t)arow * K + (kt + 1) * GBK + acol];
            bn = *(const float4*)&Bb[(size_t)((kt + 1) * GBK + brl) * N + bcl];
        }
#pragma unroll
        for (int kk = 0; kk < GBK; kk++) {
            float ra[8], rb[8];
            *(float4*)&ra[0] = *(const float4*)&As[cur][kk][tm];
            *(float4*)&ra[4] = *(const float4*)&As[cur][kk][tm + 4];
            *(float4*)&rb[0] = *(const float4*)&Bs[cur][kk][tn];
            *(float4*)&rb[4] = *(const float4*)&Bs[cur][kk][tn + 4];
#pragma unroll
            for (int i = 0; i < 8; i++)
#pragma unroll
                for (int j = 0; j < 8; j++) acc[i][j] += ra[i] * rb[j];
        }
        if (kt + 1 < nk) {
            int nxt = cur ^ 1;
            As[nxt][acol + 0][arow] = an.x;
            As[nxt][acol + 1][arow] = an.y;
            As[nxt][acol + 2][arow] = an.z;
            As[nxt][acol + 3][arow] = an.w;
            *(float4*)&Bs[nxt][brl][bcl] = bn;
            __syncthreads();
        }
    }

    float bias_r[8];
#pragma unroll
    for (int j = 0; j < 8; j++) bias_r[j] = bias[bcol * GBN + tn + j];
#pragma unroll
    for (int i = 0; i < 8; i++) {
        float4 v0 = make_float4(acc[i][0] + bias_r[0], acc[i][1] + bias_r[1],
                                acc[i][2] + bias_r[2], acc[i][3] + bias_r[3]);
        float4 v1 = make_float4(acc[i][4] + bias_r[4], acc[i][5] + bias_r[5],
                                acc[i][6] + bias_r[6], acc[i][7] + bias_r[7]);
        size_t row = (size_t)(brow * GBM + tm + i) * N + bcol * GBN + tn;
        *(float4*)&C[row]     = v0;
        *(float4*)&C[row + 4] = v1;
    }
}

// --------------------------- recurrence (per-warp dataflow) ------------------
__global__ void __launch_bounds__(256)
recur_kernel(float* __restrict__ out) {
    extern __shared__ float sm[];
    float* Us   = sm;                          // [1024][32]
    float* hs   = Us + 1024 * 32;              // [8][HS_STRIDE]
    float* part = hs + 8 * HS_STRIDE;          // [8][PART_STRIDE]

    int tid = threadIdx.x;
    int n = blockIdx.x >> 2;                   // 0..31 ntile
    int g = blockIdx.x & 3;                    // 0..3 batch group

    // load Uh column slab: Us[k][c] = Uh[k][n*32+c]
    for (int i = tid; i < 1024 * 8; i += 256) {
        int k = i >> 3, c4 = (i & 7) << 2;
        *(float4*)&Us[k * 32 + c4] =
            *(const float4*)&g_Uh[(size_t)k * DD + n * 32 + c4];
    }

    int ob = tid >> 5, oc = tid & 31;          // this thread's output element
    size_t obase = (size_t)(g * 8 + ob) * DD + n * 32 + oc;

    // t = 0: h0 = tanh(wh_out[0])
    float v0 = out[obase];
    __syncthreads();                           // Us loaded
    out[obase] = tanhf(v0);
    __syncthreads();
    if (tid == 0) st_rel(&g_done[0][g][n], 1);

    int lane = tid & 31, w = tid >> 5;
    int bg = (lane >> 3) << 1;                 // 0,2,4,6 : 2 batch rows
    int cg = (lane & 7) << 2;                  // 0..28   : 4 cols
    const int kbase = w << 7;                  // warp's K slice

    for (int t = 1; t < TT; ++t) {
        // prefetch wh for this step (exclusively ours)
        float whv = __ldcg(&out[(size_t)t * BB * DD + obase]);

        // per-warp poll: lanes 0..3 watch this warp's 4 producer flags
        {
            const int* fp = &g_done[t - 1][g][(w << 2) + lane];
            int rdy = 1;
            if (lane < 4) rdy = (ld_acq(fp) != 0);
            while (!__all_sync(0xffffffffu, rdy)) {
                if (!rdy) rdy = (ld_acq(fp) != 0);
            }
        }

        // per-warp stage: private k-slice, 8 rows x 128 cols, one shot (MLP=8)
        {
            const float* hrow = out + (size_t)(t - 1) * BB * DD
                              + (size_t)(g * 8) * DD + kbase;
            float4 v[8];
#pragma unroll
            for (int j = 0; j < 8; ++j)
                v[j] = *(const float4*)&hrow[(size_t)j * DD + (lane << 2)];
#pragma unroll
            for (int j = 0; j < 8; ++j)
                *(float4*)&hs[j * HS_STRIDE + kbase + (lane << 2)] = v[j];
        }
        __syncwarp();

        float a0[4] = {0.f, 0.f, 0.f, 0.f};
        float a1[4] = {0.f, 0.f, 0.f, 0.f};
        const float* h0p = &hs[bg * HS_STRIDE + kbase];
        const float* h1p = &hs[(bg + 1) * HS_STRIDE + kbase];
        const float* up  = &Us[kbase * 32 + cg];

#pragma unroll 4
        for (int kk = 0; kk < 128; kk += 4) {
            float h0v[4], h1v[4];
            *(float4*)h0v = *(const float4*)&h0p[kk];
            *(float4*)h1v = *(const float4*)&h1p[kk];
#pragma unroll
            for (int q = 0; q < 4; q++) {
                float uv[4];
                *(float4*)uv = *(const float4*)&up[(kk + q) * 32];
#pragma unroll
                for (int j = 0; j < 4; j++) {
                    a0[j] += h0v[q] * uv[j];
                    a1[j] += h1v[q] * uv[j];
                }
            }
        }

        // intra-CTA split-K reduce through SMEM (fixed order => deterministic)
        *(float4*)&part[w * PART_STRIDE + bg * 32 + cg]       = *(float4*)a0;
        *(float4*)&part[w * PART_STRIDE + (bg + 1) * 32 + cg] = *(float4*)a1;
        __syncthreads();

        float s = whv;
#pragma unroll
        for (int ww = 0; ww < 8; ww++) s += part[ww * PART_STRIDE + tid];
        out[(size_t)t * BB * DD + obase] = tanhf(s);

        __syncthreads();                       // all STGs + part reads done
        if (t < TT - 1 && tid == 0) st_rel(&g_done[t][g][n], 1);
    }
}

// --------------------------- launch ------------------------------------------
extern "C" void kernel_launch(void* const* d_in, const int* in_sizes, int n_in,
                              void* d_out, int out_size) {
    const float* x    = (const float*)d_in[0];
    const float* wh_r = (const float*)d_in[1];
    const float* wh_i = (const float*)d_in[2];
    const float* wh_j = (const float*)d_in[3];
    const float* wh_k = (const float*)d_in[4];
    const float* uh_r = (const float*)d_in[5];
    const float* uh_i = (const float*)d_in[6];
    const float* uh_j = (const float*)d_in[7];
    const float* uh_k = (const float*)d_in[8];
    const float* wh_b = (const float*)d_in[9];
    float* out = (float*)d_out;

    dim3 bq(DD / 256, DD);
    build_qmat_kernel<<<bq, 256>>>(wh_r, wh_i, wh_j, wh_k, 0);  // also zeroes flags
    build_qmat_kernel<<<bq, 256>>>(uh_r, uh_i, uh_j, uh_k, 1);

    dim3 gg(DD / GBN, (TT * BB) / GBM);   // (8, 128)
    sgemm_bias_kernel<<<gg, 256>>>(x, wh_b, out, TT * BB, DD, DD);

    const int smem_bytes = (1024 * 32 + 8 * HS_STRIDE + 8 * PART_STRIDE) * 4;
    cudaFuncSetAttribute(recur_kernel,
                         cudaFuncAttributeMaxDynamicSharedMemorySize, smem_bytes);
    recur_kernel<<<32 * 4, 256, smem_bytes>>>(out);
}

// round 12
// speedup vs baseline: 1.2980x; 1.2980x over previous
#include <cuda_runtime.h>
#include <math.h>

// ---------------------------------------------------------------------------
// QRNN: h_t = tanh(x_t @ Wh + b + h_{t-1} @ Uh),  T=512, B=32, D=1024
// Phase B: fp32 SGEMM (R3-proven).
// Phase C: recurrence, 128 CTAs = 32 ntiles x 4 batch groups, full-K per CTA.
//          R12 = R10 sync structure (single-warp 32-flag poll + CTA barrier)
//          with per-warp PRIVATE staging of each warp's k-slice (syncwarp
//          instead of a second CTA barrier), __ldcg streaming loads.
// ---------------------------------------------------------------------------

#define TT 512
#define BB 32
#define DD 1024
#define QQ 256

#define HS_STRIDE 1036
#define PART_STRIDE 264

__device__ float g_Wh[DD * DD];
__device__ float g_Uh[DD * DD];
__device__ int   g_done[TT][4][32];   // per (t, batch-group, ntile) flag

// ------------------------- sync primitives ----------------------------------
__device__ __forceinline__ int ld_acq(const int* p) {
    int v;
    asm volatile("ld.acquire.gpu.global.s32 %0, [%1];" : "=r"(v) : "l"(p) : "memory");
    return v;
}
__device__ __forceinline__ void st_rel(int* p, int v) {
    asm volatile("st.release.gpu.global.s32 [%0], %1;" :: "l"(p), "r"(v) : "memory");
}

// --------------------------- quaternion matrix build ------------------------
// which==0 also zeroes the flag array (rides along off the critical path).
__global__ void build_qmat_kernel(const float* __restrict__ wr,
                                  const float* __restrict__ wi,
                                  const float* __restrict__ wj,
                                  const float* __restrict__ wk,
                                  int which) {
    int e = blockIdx.x * blockDim.x + threadIdx.x;
    int d = blockIdx.y;
    if (which == 0 && d == 0) {
        for (int i = e; i < TT * 4 * 32; i += 1024)
            (&g_done[0][0][0])[i] = 0;
    }
    int br = d >> 8, bc = e >> 8;
    int r = d & 255, c = e & 255;
    int comp = br ^ bc;
    int mask = (0x5390 >> (br * 4)) & 0xF;
    float s = ((mask >> bc) & 1) ? -1.0f : 1.0f;
    const float* w = (comp == 0) ? wr : (comp == 1) ? wi : (comp == 2) ? wj : wk;
    float* W = which ? g_Uh : g_Wh;
    W[d * DD + e] = s * w[r * QQ + c];
}

// --------------------------- fp32 SGEMM (R3 version) ------------------------
#define GBM 128
#define GBN 128
#define GBK 8

__global__ void __launch_bounds__(256)
sgemm_bias_kernel(const float* __restrict__ A, const float* __restrict__ bias,
                  float* __restrict__ C, int M, int N, int K) {
    __shared__ float As[2][GBK][GBM];
    __shared__ float Bs[2][GBK][GBN];
    const float* Bmat = g_Wh;

    int tid  = threadIdx.x;
    int brow = blockIdx.y, bcol = blockIdx.x;
    int arow = tid >> 1,  acol = (tid & 1) << 2;
    int brl  = tid >> 5,  bcl  = (tid & 31) << 2;

    const float* Ab = A + (size_t)(brow * GBM) * K;
    const float* Bb = Bmat + bcol * GBN;

    float4 av = *(const float4*)&Ab[(size_t)arow * K + acol];
    float4 bv = *(const float4*)&Bb[(size_t)brl * N + bcl];
    As[0][acol + 0][arow] = av.x;
    As[0][acol + 1][arow] = av.y;
    As[0][acol + 2][arow] = av.z;
    As[0][acol + 3][arow] = av.w;
    *(float4*)&Bs[0][brl][bcl] = bv;
    __syncthreads();

    int tm = (tid >> 4) << 3;
    int tn = (tid & 15) << 3;
    float acc[8][8];
#pragma unroll
    for (int i = 0; i < 8; i++)
#pragma unroll
        for (int j = 0; j < 8; j++) acc[i][j] = 0.0f;

    int nk = K / GBK;
    for (int kt = 0; kt < nk; ++kt) {
        int cur = kt & 1;
        float4 an, bn;
        if (kt + 1 < nk) {
            an = *(const float4*)&Ab[(size_t)arow * K + (kt + 1) * GBK + acol];
            bn = *(const float4*)&Bb[(size_t)((kt + 1) * GBK + brl) * N + bcl];
        }
#pragma unroll
        for (int kk = 0; kk < GBK; kk++) {
            float ra[8], rb[8];
            *(float4*)&ra[0] = *(const float4*)&As[cur][kk][tm];
            *(float4*)&ra[4] = *(const float4*)&As[cur][kk][tm + 4];
            *(float4*)&rb[0] = *(const float4*)&Bs[cur][kk][tn];
            *(float4*)&rb[4] = *(const float4*)&Bs[cur][kk][tn + 4];
#pragma unroll
            for (int i = 0; i < 8; i++)
#pragma unroll
                for (int j = 0; j < 8; j++) acc[i][j] += ra[i] * rb[j];
        }
        if (kt + 1 < nk) {
            int nxt = cur ^ 1;
            As[nxt][acol + 0][arow] = an.x;
            As[nxt][acol + 1][arow] = an.y;
            As[nxt][acol + 2][arow] = an.z;
            As[nxt][acol + 3][arow] = an.w;
            *(float4*)&Bs[nxt][brl][bcl] = bn;
            __syncthreads();
        }
    }

    float bias_r[8];
#pragma unroll
    for (int j = 0; j < 8; j++) bias_r[j] = bias[bcol * GBN + tn + j];
#pragma unroll
    for (int i = 0; i < 8; i++) {
        float4 v0 = make_float4(acc[i][0] + bias_r[0], acc[i][1] + bias_r[1],
                                acc[i][2] + bias_r[2], acc[i][3] + bias_r[3]);
        float4 v1 = make_float4(acc[i][4] + bias_r[4], acc[i][5] + bias_r[5],
                                acc[i][6] + bias_r[6], acc[i][7] + bias_r[7]);
        size_t row = (size_t)(brow * GBM + tm + i) * N + bcol * GBN + tn;
        *(float4*)&C[row]     = v0;
        *(float4*)&C[row + 4] = v1;
    }
}

// --------------------------- recurrence -------------------------------------
// CTA (n, g): output tile = batch rows [g*8, g*8+8) x cols [n*32, n*32+32),
// full K=1024. Uh[:, n*32..n*32+32) resident in SMEM (128 KB).
// Per step: warp0 polls all 32 producer flags (one lane each), CTA barrier,
// then EACH warp stages its own k-slice (8 rows x 128, __ldcg) guarded by
// __syncwarp only, computes its partial, SMEM split-K reduce (2 barriers),
// tanh, STG, tid0 release.
__global__ void __launch_bounds__(256)
recur_kernel(float* __restrict__ out) {
    extern __shared__ float sm[];
    float* Us   = sm;                          // [1024][32]
    float* hs   = Us + 1024 * 32;              // [8][HS_STRIDE]
    float* part = hs + 8 * HS_STRIDE;          // [8][PART_STRIDE]

    int tid = threadIdx.x;
    int n = blockIdx.x >> 2;                   // 0..31 ntile
    int g = blockIdx.x & 3;                    // 0..3 batch group

    // load Uh column slab: Us[k][c] = Uh[k][n*32+c]
    for (int i = tid; i < 1024 * 8; i += 256) {
        int k = i >> 3, c4 = (i & 7) << 2;
        *(float4*)&Us[k * 32 + c4] =
            *(const float4*)&g_Uh[(size_t)k * DD + n * 32 + c4];
    }

    int ob = tid >> 5, oc = tid & 31;          // this thread's output element
    size_t obase = (size_t)(g * 8 + ob) * DD + n * 32 + oc;

    // t = 0: h0 = tanh(wh_out[0])
    float v0 = out[obase];
    __syncthreads();                           // Us loaded
    out[obase] = tanhf(v0);
    __syncthreads();
    if (tid == 0) st_rel(&g_done[0][g][n], 1);

    int lane = tid & 31, w = tid >> 5;
    int bg = (lane >> 3) << 1;                 // 0,2,4,6 : 2 batch rows
    int cg = (lane & 7) << 2;                  // 0..28   : 4 cols
    const int kbase = w << 7;                  // warp's K slice

    for (int t = 1; t < TT; ++t) {
        // prefetch wh for this step (exclusively ours) before the wait
        float whv = __ldcg(&out[(size_t)t * BB * DD + obase]);

        // parallel poll: warp 0's 32 lanes each watch one producer flag
        if (w == 0) {
            const int* fp = &g_done[t - 1][g][lane];
            int rdy = (ld_acq(fp) != 0);
            while (!__all_sync(0xffffffffu, rdy)) {
                if (!rdy) rdy = (ld_acq(fp) != 0);
            }
        }
        __syncthreads();

        // per-warp private stage: 8 rows x this warp's 128-k slice
        {
            const float* hrow = out + (size_t)(t - 1) * BB * DD
                              + (size_t)(g * 8) * DD + kbase;
            float4 v[8];
#pragma unroll
            for (int j = 0; j < 8; ++j)
                v[j] = __ldcg((const float4*)&hrow[(size_t)j * DD + (lane << 2)]);
#pragma unroll
            for (int j = 0; j < 8; ++j)
                *(float4*)&hs[j * HS_STRIDE + kbase + (lane << 2)] = v[j];
        }
        __syncwarp();

        float a0[4] = {0.f, 0.f, 0.f, 0.f};
        float a1[4] = {0.f, 0.f, 0.f, 0.f};
        const float* h0p = &hs[bg * HS_STRIDE + kbase];
        const float* h1p = &hs[(bg + 1) * HS_STRIDE + kbase];
        const float* up  = &Us[kbase * 32 + cg];

#pragma unroll 4
        for (int kk = 0; kk < 128; kk += 4) {
            float h0v[4], h1v[4];
            *(float4*)h0v = *(const float4*)&h0p[kk];
            *(float4*)h1v = *(const float4*)&h1p[kk];
#pragma unroll
            for (int q = 0; q < 4; q++) {
                float uv[4];
                *(float4*)uv = *(const float4*)&up[(kk + q) * 32];
#pragma unroll
                for (int j = 0; j < 4; j++) {
                    a0[j] += h0v[q] * uv[j];
                    a1[j] += h1v[q] * uv[j];
                }
            }
        }

        // intra-CTA split-K reduce through SMEM (fixed order => deterministic)
        *(float4*)&part[w * PART_STRIDE + bg * 32 + cg]       = *(float4*)a0;
        *(float4*)&part[w * PART_STRIDE + (bg + 1) * 32 + cg] = *(float4*)a1;
        __syncthreads();

        float s = whv;
#pragma unroll
        for (int ww = 0; ww < 8; ww++) s += part[ww * PART_STRIDE + tid];
        out[(size_t)t * BB * DD + obase] = tanhf(s);

        __syncthreads();                       // all STGs + part reads done
        if (t < TT - 1 && tid == 0) st_rel(&g_done[t][g][n], 1);
    }
}

// --------------------------- launch ------------------------------------------
extern "C" void kernel_launch(void* const* d_in, const int* in_sizes, int n_in,
                              void* d_out, int out_size) {
    const float* x    = (const float*)d_in[0];
    const float* wh_r = (const float*)d_in[1];
    const float* wh_i = (const float*)d_in[2];
    const float* wh_j = (const float*)d_in[3];
    const float* wh_k = (const float*)d_in[4];
    const float* uh_r = (const float*)d_in[5];
    const float* uh_i = (const float*)d_in[6];
    const float* uh_j = (const float*)d_in[7];
    const float* uh_k = (const float*)d_in[8];
    const float* wh_b = (const float*)d_in[9];
    float* out = (float*)d_out;

    dim3 bq(DD / 256, DD);
    build_qmat_kernel<<<bq, 256>>>(wh_r, wh_i, wh_j, wh_k, 0);  // also zeroes flags
    build_qmat_kernel<<<bq, 256>>>(uh_r, uh_i, uh_j, uh_k, 1);

    dim3 gg(DD / GBN, (TT * BB) / GBM);   // (8, 128)
    sgemm_bias_kernel<<<gg, 256>>>(x, wh_b, out, TT * BB, DD, DD);

    const int smem_bytes = (1024 * 32 + 8 * HS_STRIDE + 8 * PART_STRIDE) * 4;
    cudaFuncSetAttribute(recur_kernel,
                         cudaFuncAttributeMaxDynamicSharedMemorySize, smem_bytes);
    recur_kernel<<<32 * 4, 256, smem_bytes>>>(out);
}